// round 4
// baseline (speedup 1.0000x reference)
#include <cuda_runtime.h>
#include <cstdint>

#define DEV_INLINE __device__ __forceinline__

// Problem constants
constexpr int B  = 32;
constexpr int S  = 512;
constexpr int D  = 512;
constexpr int NS = 5;

// Recurrent kernel tiling
constexpr int RANKS     = 8;            // CTAs per cluster
constexpr int BPC       = 2;            // batches per cluster
constexpr int NCLUSTERS = B / BPC;      // 16
constexpr int COLS      = D / RANKS;    // 64 columns per CTA
constexpr int RTHREADS  = 512;

// Scratch (static device arrays; no allocations allowed)
__device__ float g_A[(size_t)B * S * D];       // H @ W1
__device__ float g_C[(size_t)B * S * D];       // H @ W2

// ---------- helpers ----------
DEV_INLINE uint64_t pack2(float lo, float hi) {
    uint64_t r; asm("mov.b64 %0, {%1, %2};" : "=l"(r) : "f"(lo), "f"(hi)); return r;
}
DEV_INLINE void unpack2(uint64_t v, float& lo, float& hi) {
    asm("mov.b64 {%0, %1}, %2;" : "=f"(lo), "=f"(hi) : "l"(v));
}
DEV_INLINE uint64_t fma2(uint64_t a, uint64_t b, uint64_t c) {
    uint64_t d; asm("fma.rn.f32x2 %0, %1, %2, %3;" : "=l"(d) : "l"(a), "l"(b), "l"(c));
    return d;
}
DEV_INLINE uint64_t add2(uint64_t a, uint64_t b) {
    uint64_t d; asm("add.rn.f32x2 %0, %1, %2;" : "=l"(d) : "l"(a), "l"(b));
    return d;
}
DEV_INLINE uint32_t su32(const void* p) {
    uint32_t a;
    asm("{ .reg .u64 t; cvta.to.shared.u64 t, %1; cvt.u32.u64 %0, t; }" : "=r"(a) : "l"(p));
    return a;
}
DEV_INLINE void stc_f32(uint32_t saddr, int rank, float v) {
    asm volatile("{ .reg .b32 r; mapa.shared::cluster.u32 r, %0, %1; st.shared::cluster.f32 [r], %2; }"
                 :: "r"(saddr), "r"(rank), "f"(v) : "memory");
}
DEV_INLINE void stc_b64(uint32_t saddr, int rank, uint64_t v) {
    asm volatile("{ .reg .b32 r; mapa.shared::cluster.u32 r, %0, %1; st.shared::cluster.b64 [r], %2; }"
                 :: "r"(saddr), "r"(rank), "l"(v) : "memory");
}
DEV_INLINE void cluster_arrive() {
    asm volatile("barrier.cluster.arrive.aligned;" ::: "memory");
}
DEV_INLINE void cluster_wait() {
    asm volatile("barrier.cluster.wait.aligned;"   ::: "memory");
}
// fast tanh via __expf, clamped so exp never overflows
DEV_INLINE float ftanh(float x) {
    x = fminf(15.f, fmaxf(-15.f, x));
    float e = __expf(x + x);
    return __fdividef(e - 1.f, e + 1.f);
}

// ============================================================
// Precompute: A = H @ W1, C = H @ W2   (fp32, f32x2 FMAs)
// ============================================================
constexpr int PM = 128, PN = 128, PK = 16;

__global__ __launch_bounds__(256) void precompute_kernel(
    const float* __restrict__ Hm,
    const float* __restrict__ W1,
    const float* __restrict__ W2)
{
    __shared__ float As[PK][PM];
    __shared__ float Bs[PK][PN];

    const int tid   = threadIdx.x;
    const int which = blockIdx.y >> 2;
    const int n0    = (blockIdx.y & 3) * PN;
    const int m0    = blockIdx.x * PM;
    const float* W  = which ? W2 : W1;
    float* OUT      = which ? g_C : g_A;

    const int tx = tid & 15;
    const int ty = tid >> 4;

    uint64_t acc[8][4];
    #pragma unroll
    for (int i = 0; i < 8; i++)
        #pragma unroll
        for (int j = 0; j < 4; j++) acc[i][j] = 0ull;

    for (int kt = 0; kt < 512; kt += PK) {
        #pragma unroll
        for (int i = 0; i < 2; i++) {
            int idx4 = i * 256 + tid;
            int m  = idx4 >> 2;
            int kq = (idx4 & 3) * 4;
            float4 vv = *(const float4*)&Hm[(size_t)(m0 + m) * 512 + kt + kq];
            As[kq + 0][m] = vv.x; As[kq + 1][m] = vv.y;
            As[kq + 2][m] = vv.z; As[kq + 3][m] = vv.w;
        }
        #pragma unroll
        for (int i = 0; i < 2; i++) {
            int idx4 = i * 256 + tid;
            int n4 = (idx4 & 31) * 4;
            int k  = idx4 >> 5;
            *(float4*)&Bs[k][n4] = *(const float4*)&W[(size_t)(kt + k) * 512 + n0 + n4];
        }
        __syncthreads();

        #pragma unroll
        for (int k = 0; k < PK; k++) {
            float4 a0 = *(const float4*)&As[k][ty * 8];
            float4 a1 = *(const float4*)&As[k][ty * 8 + 4];
            float4 b0 = *(const float4*)&Bs[k][tx * 8];
            float4 b1 = *(const float4*)&Bs[k][tx * 8 + 4];
            float av[8] = {a0.x, a0.y, a0.z, a0.w, a1.x, a1.y, a1.z, a1.w};
            uint64_t bp[4];
            bp[0] = pack2(b0.x, b0.y); bp[1] = pack2(b0.z, b0.w);
            bp[2] = pack2(b1.x, b1.y); bp[3] = pack2(b1.z, b1.w);
            #pragma unroll
            for (int i = 0; i < 8; i++) {
                uint64_t ad = pack2(av[i], av[i]);
                #pragma unroll
                for (int j = 0; j < 4; j++)
                    acc[i][j] = fma2(ad, bp[j], acc[i][j]);
            }
        }
        __syncthreads();
    }

    #pragma unroll
    for (int i = 0; i < 8; i++) {
        int row = m0 + ty * 8 + i;
        float f0, f1, f2, f3, f4, f5, f6, f7;
        unpack2(acc[i][0], f0, f1); unpack2(acc[i][1], f2, f3);
        unpack2(acc[i][2], f4, f5); unpack2(acc[i][3], f6, f7);
        *(float4*)&OUT[(size_t)row * 512 + n0 + tx * 8]     = make_float4(f0, f1, f2, f3);
        *(float4*)&OUT[(size_t)row * 512 + n0 + tx * 8 + 4] = make_float4(f4, f5, f6, f7);
    }
}

// ============================================================
// Recurrent kernel, software-pipelined across both barriers.
// Fix vs R3: no remote DSMEM store may be issued at t=S-1 without a
// subsequent cluster barrier (peer could have exited). The final g-push
// is skipped (never consumed) and a terminal cluster sync guarantees
// CTA lifetime for all earlier remote stores.
// ============================================================
__global__ __launch_bounds__(RTHREADS, 1) __cluster_dims__(RANKS, 1, 1)
void recurrent_kernel(const float* __restrict__ Hm,
                      const float* __restrict__ v,
                      const float* __restrict__ W3,
                      float* __restrict__ out)
{
    __shared__ float4   hts_dup4[COLS];            // (h0,h0,h1,h1) per own k
    __shared__ float    thist[NS][BPC][COLS];      // htilde history (own cols)
    __shared__ float    ghist[NS][BPC][COLS];      // summed g history (own cols)
    __shared__ float2   gpart2[RANKS][COLS];       // recv: partial g (b0,b1)/col
    __shared__ float    spart[2][BPC][NS][RANKS];  // recv: logit partials, parity
    __shared__ float    pbufA[2][BPC * NS][COLS];  // prefetched g_A rows
    __shared__ float    pbufC[2][BPC][COLS];       // prefetched g_C rows
    __shared__ float    hbuf[2][BPC][COLS];        // prefetched H rows
    __shared__ uint64_t red2[256][2];              // P3 k-half partials
    __shared__ float    vsm[COLS];
    __shared__ float    ssm[BPC * NS];
    __shared__ float    wsm[BPC][NS];

    const int tid  = threadIdx.x;
    const int warp = tid >> 5, lane = tid & 31;
    const int rank = blockIdx.x & (RANKS - 1);
    const int cl   = blockIdx.x >> 3;
    const int col0 = rank * COLS;
    const int b0   = cl * BPC;

    // ---- P3 identities: thread owns cols (2p, 2p+1), k-half ----
    const int pairIdx = tid & 255;
    const int khalf   = tid >> 8;
    const int gcol    = pairIdx * 2;
    const int grank   = pairIdx >> 5;          // target rank for g push

    // W3 slice: 32 k-rows x 2 adjacent cols, pair-packed (2 distinct weights)
    uint64_t w3p[32];
    #pragma unroll
    for (int kk = 0; kk < 32; kk++)
        w3p[kk] = *(const uint64_t*)&W3[(size_t)(col0 + khalf * 32 + kk) * D + gcol];

    if (tid < COLS) vsm[tid] = v[col0 + tid];
    for (int i = tid; i < NS * BPC * COLS; i += RTHREADS) {
        ((float*)ghist)[i] = 0.f;
        ((float*)thist)[i] = 0.f;
    }

    // loader ids (warps 10-15)
    const int lidx = tid - 320;
    const int lrow = lidx >> 4;            // 0..11
    const int lq   = (lidx & 15) * 4;
    const int lbl  = (lidx >> 4) & 1;      // H-row batch for lidx<32

    // P1 ids
    const int p1bl = (warp < 10) ? warp / NS : 0;
    const int p1i  = (warp < 10) ? warp % NS : 0;
    const int d0   = lane * 2;
    uint32_t spush[2];
    spush[0] = su32(&spart[0][p1bl][p1i][rank]);
    spush[1] = su32(&spart[1][p1bl][p1i][rank]);

    const uint32_t raddr = su32(&red2[pairIdx][0]);
    const uint32_t gpa0  = su32(&gpart2[rank][gcol & 63]);
    const uint32_t gpa1  = gpa0 + 8;
    const uint32_t hbase = su32(&hts_dup4[khalf * 32]);

    // ---- prologue: load t=0 C/H rows straight into buffers ----
    if (warp >= 10) {
        if (lrow >= 10)
            *(float4*)&pbufC[0][lrow - 10][lq] =
                __ldcs((const float4*)&g_C[((size_t)(b0 + lrow - 10) * S + 0) * D + col0 + lq]);
        if (lidx < 32)
            *(float4*)&hbuf[0][lbl][lq] =
                *(const float4*)&Hm[((size_t)(b0 + lbl) * S + 0) * D + col0 + lq];
    }
    __syncthreads();

    // prologue P1-pre for t=0 (i<4 warps; all j<0 -> c-only)
    if (warp < 10 && p1i != NS - 1) {
        float2 c2 = *(float2*)&pbufC[0][p1bl][d0];
        float val = ftanh(c2.x) * vsm[d0] + ftanh(c2.y) * vsm[d0 + 1];
        #pragma unroll
        for (int o = 16; o > 0; o >>= 1)
            val += __shfl_down_sync(0xffffffffu, val, o);
        if (lane == 0) {
            #pragma unroll
            for (int r = 0; r < RANKS; r++) stc_f32(spush[0], r, val);
        }
    }

    // prologue: issue LDGs for t=1 (distance-2 prefetch pipeline)
    float4 pvA = make_float4(0.f, 0.f, 0.f, 0.f);
    float4 pvH = make_float4(0.f, 0.f, 0.f, 0.f);
    int pfrow = -1; bool pfH = false;
    if (warp >= 10) {
        const int tload = 1;
        if (lrow < 10) {
            int jbl = lrow / NS, ji = lrow % NS, j = tload - NS + ji;
            if (j >= 0) {
                pvA = __ldcs((const float4*)&g_A[((size_t)(b0 + jbl) * S + j) * D + col0 + lq]);
                pfrow = lrow;
            }
        } else {
            pvA = __ldcs((const float4*)&g_C[((size_t)(b0 + lrow - 10) * S + tload) * D + col0 + lq]);
            pfrow = lrow;
        }
        if (lidx < 32) {
            pvH = *(const float4*)&Hm[((size_t)(b0 + lbl) * S + tload) * D + col0 + lq];
            pfH = true;
        }
    }

    for (int t = 0; t < S; t++) {
        const int par = t & 1;

        if (t > 0) cluster_wait();   // barrier B: gpart(t-1) visible

        // ---- critical section: only i==NS-1 warps (4, 9) ----
        if (warp < 10 && p1i == NS - 1) {
            float2 c2 = *(float2*)&pbufC[par][p1bl][d0];
            float x0 = c2.x, x1 = c2.y;
            const int j = t - 1;
            if (j >= 0) {
                float2 a2 = *(float2*)&pbufA[par][warp][d0];
                float g0 = 0.f, g1 = 0.f;
                #pragma unroll
                for (int r = 0; r < RANKS; r++) {
                    float4 qv = *(float4*)&gpart2[r][d0];
                    if (p1bl == 0) { g0 += qv.x; g1 += qv.z; }
                    else           { g0 += qv.y; g1 += qv.w; }
                }
                ghist[j % NS][p1bl][d0]     = g0;
                ghist[j % NS][p1bl][d0 + 1] = g1;
                x0 += a2.x + g0;
                x1 += a2.y + g1;
            }
            float val = ftanh(x0) * vsm[d0] + ftanh(x1) * vsm[d0 + 1];
            #pragma unroll
            for (int o = 16; o > 0; o >>= 1)
                val += __shfl_down_sync(0xffffffffu, val, o);
            if (lane == 0) {
                #pragma unroll
                for (int r = 0; r < RANKS; r++) stc_f32(spush[par], r, val);
            }
        }
        cluster_arrive();            // barrier A arrive (s-partials released)

        // ---- overlapped with barrier A: prefetch deposit + next issue ----
        if (warp >= 10) {
            if (pfrow >= 0) {
                if (pfrow < 10) *(float4*)&pbufA[par ^ 1][pfrow][lq]      = pvA;
                else            *(float4*)&pbufC[par ^ 1][pfrow - 10][lq] = pvA;
            }
            if (pfH) *(float4*)&hbuf[par ^ 1][lbl][lq] = pvH;
            pfrow = -1; pfH = false;
            const int tload = t + 2;
            if (tload < S) {
                if (lrow < 10) {
                    int jbl = lrow / NS, ji = lrow % NS, j = tload - NS + ji;
                    if (j >= 0) {
                        pvA = __ldcs((const float4*)&g_A[((size_t)(b0 + jbl) * S + j) * D + col0 + lq]);
                        pfrow = lrow;
                    }
                } else {
                    pvA = __ldcs((const float4*)&g_C[((size_t)(b0 + lrow - 10) * S + tload) * D + col0 + lq]);
                    pfrow = lrow;
                }
                if (lidx < 32) {
                    pvH = *(const float4*)&Hm[((size_t)(b0 + lbl) * S + tload) * D + col0 + lq];
                    pfH = true;
                }
            }
        }
        cluster_wait();              // barrier A: s-partials visible

        // ---- softmax (warp 0) ----
        if (warp == 0) {
            if (lane < BPC * NS) {
                const int bl = lane / NS, i = lane - bl * NS;
                float4 u0 = *(float4*)&spart[par][bl][i][0];
                float4 u1 = *(float4*)&spart[par][bl][i][4];
                ssm[lane] = (u0.x + u0.y + u0.z + u0.w) + (u1.x + u1.y + u1.z + u1.w);
            }
            __syncwarp();
            if (lane < BPC) {
                float s[NS];
                #pragma unroll
                for (int i = 0; i < NS; i++) s[i] = ssm[lane * NS + i];
                float m = s[0];
                #pragma unroll
                for (int i = 1; i < NS; i++) m = fmaxf(m, s[i]);
                float e[NS], sum = 0.f;
                #pragma unroll
                for (int i = 0; i < NS; i++) { e[i] = __expf(s[i] - m); sum += e[i]; }
                float inv = __fdividef(1.f, sum);
                #pragma unroll
                for (int i = 0; i < NS; i++) wsm[lane][i] = e[i] * inv;
            }
        }
        __syncthreads();

        // ---- htilde (own cols) ----
        if (tid < BPC * COLS) {
            const int bl = tid >> 6, dd = tid & 63;
            float hh = 0.f;
            #pragma unroll
            for (int i = 0; i < NS; i++) {
                int j = t - NS + i;
                if (j >= 0) hh += wsm[bl][i] * thist[j % NS][bl][dd];
            }
            float hv = hbuf[par][bl][dd] + fmaxf(hh, 0.f);
            thist[t % NS][bl][dd] = hv;
            *(float2*)((float*)&hts_dup4[dd] + 2 * bl) = make_float2(hv, hv);
            __stcs(&out[((size_t)(b0 + bl) * S + t) * D + col0 + dd], hv);
        }
        __syncthreads();

        // ---- P3: partial g over k-half, 2 cols x 2 batches per thread ----
        // (skipped at t=S-1: result never consumed, and remote stores at the
        //  final step would race with peer CTA exit)
        if (t < S - 1) {
            uint64_t acc0 = 0ull, acc1 = 0ull;   // (col2p,col2p+1) for b0 / b1
            #pragma unroll
            for (int kk = 0; kk < 32; kk++) {
                uint64_t h0d, h1d;
                asm volatile("ld.shared.v2.u64 {%0, %1}, [%2];"
                             : "=l"(h0d), "=l"(h1d) : "r"(hbase + kk * 16));
                acc0 = fma2(h0d, w3p[kk], acc0);
                acc1 = fma2(h1d, w3p[kk], acc1);
            }
            if (khalf) {
                asm volatile("st.shared.v2.u64 [%0], {%1, %2};"
                             :: "r"(raddr), "l"(acc0), "l"(acc1) : "memory");
            }
            __syncthreads();
            if (!khalf) {
                uint64_t r0, r1;
                asm volatile("ld.shared.v2.u64 {%0, %1}, [%2];"
                             : "=l"(r0), "=l"(r1) : "r"(raddr));
                acc0 = add2(acc0, r0);
                acc1 = add2(acc1, r1);
                float c0b0, c1b0, c0b1, c1b1;
                unpack2(acc0, c0b0, c1b0);
                unpack2(acc1, c0b1, c1b1);
                stc_b64(gpa0, grank, pack2(c0b0, c0b1));   // col 2p:   (b0,b1)
                stc_b64(gpa1, grank, pack2(c1b0, c1b1));   // col 2p+1: (b0,b1)
            }
            cluster_arrive();   // barrier B arrive (g released)

            // ---- P1-pre for t+1 (i<4 warps) — hidden behind barrier B ----
            if (warp < 10 && p1i != NS - 1) {
                float2 c2 = *(float2*)&pbufC[par ^ 1][p1bl][d0];
                float x0 = c2.x, x1 = c2.y;
                const int j = (t + 1) - NS + p1i;
                if (j >= 0) {
                    float2 a2 = *(float2*)&pbufA[par ^ 1][warp][d0];
                    x0 += a2.x + ghist[j % NS][p1bl][d0];
                    x1 += a2.y + ghist[j % NS][p1bl][d0 + 1];
                }
                float val = ftanh(x0) * vsm[d0] + ftanh(x1) * vsm[d0 + 1];
                #pragma unroll
                for (int o = 16; o > 0; o >>= 1)
                    val += __shfl_down_sync(0xffffffffu, val, o);
                if (lane == 0) {
                    #pragma unroll
                    for (int r = 0; r < RANKS; r++) stc_f32(spush[par ^ 1], r, val);
                }
            }
        }
    }

    // Terminal cluster sync: no CTA exits while peers' remote stores /
    // barrier phases could still reference its SMEM.
    cluster_arrive();
    cluster_wait();
}

// ============================================================
// Launch
// ============================================================
extern "C" void kernel_launch(void* const* d_in, const int* in_sizes, int n_in,
                              void* d_out, int out_size)
{
    (void)in_sizes; (void)n_in; (void)out_size;
    const float* H  = (const float*)d_in[0];
    const float* v  = (const float*)d_in[1];
    const float* W1 = (const float*)d_in[2];
    const float* W2 = (const float*)d_in[3];
    const float* W3 = (const float*)d_in[4];
    float* out = (float*)d_out;

    precompute_kernel<<<dim3((B * S) / PM, 8), 256>>>(H, W1, W2);
    recurrent_kernel<<<NCLUSTERS * RANKS, RTHREADS>>>(H, v, W3, out);
}

// round 5
// speedup vs baseline: 1.4530x; 1.4530x over previous
#include <cuda_runtime.h>
#include <cstdint>

#define DEV_INLINE __device__ __forceinline__

// Problem constants
constexpr int B  = 32;
constexpr int S  = 512;
constexpr int D  = 512;
constexpr int NS = 5;

// Recurrent kernel tiling
constexpr int RANKS     = 8;            // CTAs per cluster
constexpr int BPC       = 2;            // batches per cluster
constexpr int NCLUSTERS = B / BPC;      // 16
constexpr int COLS      = D / RANKS;    // 64 columns per CTA
constexpr int RTHREADS  = 512;

// mbarrier tx budgets (bytes)
constexpr uint32_t TX_G = 8192;  // 8 src * 128 pushes * 8B
constexpr uint32_t TX_S = 320;   // (64 pre + 16 critical) * 4B

// Scratch (static device arrays; no allocations allowed)
__device__ float g_A[(size_t)B * S * D];       // H @ W1
__device__ float g_C[(size_t)B * S * D];       // H @ W2

// ---------- helpers ----------
DEV_INLINE uint64_t pack2(float lo, float hi) {
    uint64_t r; asm("mov.b64 %0, {%1, %2};" : "=l"(r) : "f"(lo), "f"(hi)); return r;
}
DEV_INLINE void unpack2(uint64_t v, float& lo, float& hi) {
    asm("mov.b64 {%0, %1}, %2;" : "=f"(lo), "=f"(hi) : "l"(v));
}
DEV_INLINE uint64_t fma2(uint64_t a, uint64_t b, uint64_t c) {
    uint64_t d; asm("fma.rn.f32x2 %0, %1, %2, %3;" : "=l"(d) : "l"(a), "l"(b), "l"(c));
    return d;
}
DEV_INLINE uint64_t add2(uint64_t a, uint64_t b) {
    uint64_t d; asm("add.rn.f32x2 %0, %1, %2;" : "=l"(d) : "l"(a), "l"(b));
    return d;
}
DEV_INLINE uint32_t su32(const void* p) {
    uint32_t a;
    asm("{ .reg .u64 t; cvta.to.shared.u64 t, %1; cvt.u32.u64 %0, t; }" : "=r"(a) : "l"(p));
    return a;
}
DEV_INLINE uint32_t mapa_u32(uint32_t a, int rank) {
    uint32_t r; asm("mapa.shared::cluster.u32 %0, %1, %2;" : "=r"(r) : "r"(a), "r"(rank));
    return r;
}
// Remote store with mbarrier tx-completion (data+mbar in SAME target CTA)
DEV_INLINE void stasync_b32(uint32_t daddr, uint32_t mbar, int rank, uint32_t v) {
    asm volatile(
        "{ .reg .b32 rd, rm;\n\t"
        "mapa.shared::cluster.u32 rd, %0, %2;\n\t"
        "mapa.shared::cluster.u32 rm, %1, %2;\n\t"
        "st.async.shared::cluster.mbarrier::complete_tx::bytes.b32 [rd], %3, [rm]; }"
        :: "r"(daddr), "r"(mbar), "r"(rank), "r"(v) : "memory");
}
DEV_INLINE void stasync_b64_pre(uint32_t rdaddr, uint32_t rmbar, uint64_t v) {
    asm volatile(
        "st.async.shared::cluster.mbarrier::complete_tx::bytes.b64 [%0], %1, [%2];"
        :: "r"(rdaddr), "l"(v), "r"(rmbar) : "memory");
}
DEV_INLINE void mbar_init(uint32_t a, uint32_t cnt) {
    asm volatile("mbarrier.init.shared.b64 [%0], %1;" :: "r"(a), "r"(cnt) : "memory");
}
DEV_INLINE void mbar_arrive_expect(uint32_t a, uint32_t tx) {
    asm volatile("mbarrier.arrive.expect_tx.shared.b64 _, [%0], %1;"
                 :: "r"(a), "r"(tx) : "memory");
}
DEV_INLINE void mbar_wait(uint32_t mbar, uint32_t parity) {
    asm volatile(
        "{\n\t"
        ".reg .pred P;\n\t"
        "WAIT_%=:\n\t"
        "mbarrier.try_wait.parity.acquire.cluster.shared::cta.b64 P, [%0], %1, 0x989680;\n\t"
        "@P bra.uni DONE_%=;\n\t"
        "bra.uni WAIT_%=;\n\t"
        "DONE_%=:\n\t"
        "}"
        :: "r"(mbar), "r"(parity) : "memory");
}
DEV_INLINE void cluster_sync() {
    asm volatile("barrier.cluster.arrive.aligned;" ::: "memory");
    asm volatile("barrier.cluster.wait.aligned;"   ::: "memory");
}
// fast tanh via __expf, clamped so exp never overflows
DEV_INLINE float ftanh(float x) {
    x = fminf(15.f, fmaxf(-15.f, x));
    float e = __expf(x + x);
    return __fdividef(e - 1.f, e + 1.f);
}

// ============================================================
// Precompute: A = H @ W1, C = H @ W2   (fp32, f32x2 FMAs)
// ============================================================
constexpr int PM = 128, PN = 128, PK = 16;

__global__ __launch_bounds__(256) void precompute_kernel(
    const float* __restrict__ Hm,
    const float* __restrict__ W1,
    const float* __restrict__ W2)
{
    __shared__ float As[PK][PM];
    __shared__ float Bs[PK][PN];

    const int tid   = threadIdx.x;
    const int which = blockIdx.y >> 2;
    const int n0    = (blockIdx.y & 3) * PN;
    const int m0    = blockIdx.x * PM;
    const float* W  = which ? W2 : W1;
    float* OUT      = which ? g_C : g_A;

    const int tx = tid & 15;
    const int ty = tid >> 4;

    uint64_t acc[8][4];
    #pragma unroll
    for (int i = 0; i < 8; i++)
        #pragma unroll
        for (int j = 0; j < 4; j++) acc[i][j] = 0ull;

    for (int kt = 0; kt < 512; kt += PK) {
        #pragma unroll
        for (int i = 0; i < 2; i++) {
            int idx4 = i * 256 + tid;
            int m  = idx4 >> 2;
            int kq = (idx4 & 3) * 4;
            float4 vv = *(const float4*)&Hm[(size_t)(m0 + m) * 512 + kt + kq];
            As[kq + 0][m] = vv.x; As[kq + 1][m] = vv.y;
            As[kq + 2][m] = vv.z; As[kq + 3][m] = vv.w;
        }
        #pragma unroll
        for (int i = 0; i < 2; i++) {
            int idx4 = i * 256 + tid;
            int n4 = (idx4 & 31) * 4;
            int k  = idx4 >> 5;
            *(float4*)&Bs[k][n4] = *(const float4*)&W[(size_t)(kt + k) * 512 + n0 + n4];
        }
        __syncthreads();

        #pragma unroll
        for (int k = 0; k < PK; k++) {
            float4 a0 = *(const float4*)&As[k][ty * 8];
            float4 a1 = *(const float4*)&As[k][ty * 8 + 4];
            float4 b0 = *(const float4*)&Bs[k][tx * 8];
            float4 b1 = *(const float4*)&Bs[k][tx * 8 + 4];
            float av[8] = {a0.x, a0.y, a0.z, a0.w, a1.x, a1.y, a1.z, a1.w};
            uint64_t bp[4];
            bp[0] = pack2(b0.x, b0.y); bp[1] = pack2(b0.z, b0.w);
            bp[2] = pack2(b1.x, b1.y); bp[3] = pack2(b1.z, b1.w);
            #pragma unroll
            for (int i = 0; i < 8; i++) {
                uint64_t ad = pack2(av[i], av[i]);
                #pragma unroll
                for (int j = 0; j < 4; j++)
                    acc[i][j] = fma2(ad, bp[j], acc[i][j]);
            }
        }
        __syncthreads();
    }

    #pragma unroll
    for (int i = 0; i < 8; i++) {
        int row = m0 + ty * 8 + i;
        float f0, f1, f2, f3, f4, f5, f6, f7;
        unpack2(acc[i][0], f0, f1); unpack2(acc[i][1], f2, f3);
        unpack2(acc[i][2], f4, f5); unpack2(acc[i][3], f6, f7);
        *(float4*)&OUT[(size_t)row * 512 + n0 + tx * 8]     = make_float4(f0, f1, f2, f3);
        *(float4*)&OUT[(size_t)row * 512 + n0 + tx * 8 + 4] = make_float4(f4, f5, f6, f7);
    }
}

// ============================================================
// Recurrent kernel: point-to-point st.async + mbarrier signaling.
// No cluster barriers in the steady state.
// ============================================================
__global__ __launch_bounds__(RTHREADS, 1) __cluster_dims__(RANKS, 1, 1)
void recurrent_kernel(const float* __restrict__ Hm,
                      const float* __restrict__ v,
                      const float* __restrict__ W3,
                      float* __restrict__ out)
{
    __shared__ float2   hdup[BPC][COLS];             // (hv,hv) per batch/own col
    __shared__ float    thist[NS][BPC][COLS];        // htilde history
    __shared__ float    ghist[NS][BPC][COLS];        // summed g history
    __shared__ uint64_t gpartB[RANKS][2][BPC][32];   // [src][khalf][bl][pair]
    __shared__ float    spart[2][BPC][NS][RANKS];    // logit partials, parity
    __shared__ float    pbufA[2][BPC * NS][COLS];    // prefetched g_A rows
    __shared__ float    pbufC[2][BPC][COLS];         // prefetched g_C rows
    __shared__ float    hbuf[2][BPC][COLS];          // prefetched H rows
    __shared__ float    vsm[COLS];
    __shared__ float    ssm[BPC * NS];
    __shared__ float    wsm[BPC][NS];
    __shared__ uint64_t mbars[6];                    // [0..1]=g ring, [2..5]=s ring

    const int tid  = threadIdx.x;
    const int warp = tid >> 5, lane = tid & 31;
    const int rank = blockIdx.x & (RANKS - 1);
    const int cl   = blockIdx.x >> 3;
    const int col0 = rank * COLS;
    const int b0   = cl * BPC;

    const uint32_t mg_base = su32(&mbars[0]);        // + 8*b  (b = 0,1)
    const uint32_t ms_base = su32(&mbars[2]);        // + 8*k  (k = 0..3)

    // ---- init mbarriers, then cluster-wide visibility ----
    if (tid == 0) {
        #pragma unroll
        for (int i = 0; i < 6; i++) mbar_init(su32(&mbars[i]), 1);
        mbar_arrive_expect(mg_base + 0, TX_G);       // g data t=0
        mbar_arrive_expect(mg_base + 8, TX_G);       // g data t=1
        #pragma unroll
        for (int k = 0; k < 4; k++) mbar_arrive_expect(ms_base + 8 * k, TX_S);
    }
    if (tid < COLS) vsm[tid] = v[col0 + tid];
    for (int i = tid; i < NS * BPC * COLS; i += RTHREADS) {
        ((float*)ghist)[i] = 0.f;
        ((float*)thist)[i] = 0.f;
    }
    __syncthreads();
    cluster_sync();   // all mbarriers initialized before any remote st.async

    // ---- P3 identities: thread owns col pair (2p, 2p+1), k-half ----
    const int pairIdx = tid & 255;
    const int khalf   = tid >> 8;
    const int gcol    = pairIdx * 2;
    const int gdst    = pairIdx >> 5;                // destination rank
    // precomputed remote addresses for the g pushes
    const uint32_t grd0 = mapa_u32(su32(&gpartB[rank][khalf][0][pairIdx & 31]), gdst);
    const uint32_t grd1 = mapa_u32(su32(&gpartB[rank][khalf][1][pairIdx & 31]), gdst);
    uint32_t grm[2];
    grm[0] = mapa_u32(mg_base + 0, gdst);
    grm[1] = mapa_u32(mg_base + 8, gdst);

    // W3 slice: 32 k-rows x 2 adjacent cols, pair-packed
    uint64_t w3p[32];
    #pragma unroll
    for (int kk = 0; kk < 32; kk++)
        w3p[kk] = *(const uint64_t*)&W3[(size_t)(col0 + khalf * 32 + kk) * D + gcol];

    // loader ids (warps 10-15)
    const int lidx = tid - 320;
    const int lrow = lidx >> 4;            // 0..11
    const int lq   = (lidx & 15) * 4;
    const int lbl  = (lidx >> 4) & 1;

    // P1 ids
    const int p1bl = (warp < 10) ? warp / NS : 0;
    const int p1i  = (warp < 10) ? warp % NS : 0;
    const int d0   = lane * 2;
    uint32_t spush[2];
    spush[0] = su32(&spart[0][p1bl][p1i][rank]);
    spush[1] = su32(&spart[1][p1bl][p1i][rank]);

    // mbarrier phase parities (per-thread where used)
    int pg0 = 0, pg1 = 0;
    int ps0 = 0, ps1 = 0, ps2 = 0, ps3 = 0;

    // ---- prologue: load t=0 C/H rows ----
    if (warp >= 10) {
        if (lrow >= 10)
            *(float4*)&pbufC[0][lrow - 10][lq] =
                __ldcs((const float4*)&g_C[((size_t)(b0 + lrow - 10) * S + 0) * D + col0 + lq]);
        if (lidx < 32)
            *(float4*)&hbuf[0][lbl][lq] =
                *(const float4*)&Hm[((size_t)(b0 + lbl) * S + 0) * D + col0 + lq];
    }
    __syncthreads();

    // prologue P1-pre for t=0 (i<4 warps; all j<0 -> c-only)
    if (warp < 10 && p1i != NS - 1) {
        float2 c2 = *(float2*)&pbufC[0][p1bl][d0];
        float val = ftanh(c2.x) * vsm[d0] + ftanh(c2.y) * vsm[d0 + 1];
        #pragma unroll
        for (int o = 16; o > 0; o >>= 1)
            val += __shfl_down_sync(0xffffffffu, val, o);
        if (lane == 0) {
            #pragma unroll
            for (int r = 0; r < RANKS; r++)
                stasync_b32(spush[0], ms_base + 0, r, __float_as_uint(val));
        }
    }

    // prologue: issue LDGs for t=1
    float4 pvA = make_float4(0.f, 0.f, 0.f, 0.f);
    float4 pvH = make_float4(0.f, 0.f, 0.f, 0.f);
    int pfrow = -1; bool pfH = false;
    if (warp >= 10) {
        if (lrow < 10) {
            int jbl = lrow / NS, ji = lrow % NS, j = 1 - NS + ji;
            if (j >= 0) {
                pvA = __ldcs((const float4*)&g_A[((size_t)(b0 + jbl) * S + j) * D + col0 + lq]);
                pfrow = lrow;
            }
        } else {
            pvA = __ldcs((const float4*)&g_C[((size_t)(b0 + lrow - 10) * S + 1) * D + col0 + lq]);
            pfrow = lrow;
        }
        if (lidx < 32) {
            pvH = *(const float4*)&Hm[((size_t)(b0 + lbl) * S + 1) * D + col0 + lq];
            pfH = true;
        }
    }

    for (int t = 0; t < S; t++) {
        const int par = t & 1;
        const int sk  = t & 3;

        // ---- critical warps (4, 9): wait g(t-1), sum, logit, push s ----
        if (warp < 10 && p1i == NS - 1) {
            const int j = t - 1;
            if (j >= 0) {
                const int gb = (t - 1) & 1;
                mbar_wait(mg_base + 8 * gb, gb ? pg1 : pg0);
                if (gb) pg1 ^= 1; else pg0 ^= 1;
                if (warp == 4 && lane == 0)   // re-arm for data t+1
                    mbar_arrive_expect(mg_base + 8 * gb, TX_G);
            }
            float2 c2 = *(float2*)&pbufC[par][p1bl][d0];
            float x0 = c2.x, x1 = c2.y;
            if (j >= 0) {
                float2 a2 = *(float2*)&pbufA[par][warp][d0];
                uint64_t s = 0ull;
                #pragma unroll
                for (int r = 0; r < RANKS; r++) {
                    s = add2(s, gpartB[r][0][p1bl][lane]);
                    s = add2(s, gpartB[r][1][p1bl][lane]);
                }
                float g0, g1;
                unpack2(s, g0, g1);
                *(float2*)&ghist[j % NS][p1bl][d0] = make_float2(g0, g1);
                x0 += a2.x + g0;
                x1 += a2.y + g1;
            }
            float val = ftanh(x0) * vsm[d0] + ftanh(x1) * vsm[d0 + 1];
            #pragma unroll
            for (int o = 16; o > 0; o >>= 1)
                val += __shfl_down_sync(0xffffffffu, val, o);
            if (lane == 0) {
                #pragma unroll
                for (int r = 0; r < RANKS; r++)
                    stasync_b32(spush[par], ms_base + 8 * sk, r, __float_as_uint(val));
            }
        }

        // ---- warp 0: wait s, softmax ----
        if (warp == 0) {
            int psv = (sk == 0) ? ps0 : (sk == 1) ? ps1 : (sk == 2) ? ps2 : ps3;
            mbar_wait(ms_base + 8 * sk, psv);
            if (sk == 0) ps0 ^= 1; else if (sk == 1) ps1 ^= 1;
            else if (sk == 2) ps2 ^= 1; else ps3 ^= 1;
            if (lane == 0)
                mbar_arrive_expect(ms_base + 8 * sk, TX_S);   // re-arm for t+4
            if (lane < BPC * NS) {
                const int bl = lane / NS, i = lane - bl * NS;
                float4 u0 = *(float4*)&spart[par][bl][i][0];
                float4 u1 = *(float4*)&spart[par][bl][i][4];
                ssm[lane] = (u0.x + u0.y + u0.z + u0.w) + (u1.x + u1.y + u1.z + u1.w);
            }
            __syncwarp();
            if (lane < BPC) {
                float s[NS];
                #pragma unroll
                for (int i = 0; i < NS; i++) s[i] = ssm[lane * NS + i];
                float m = s[0];
                #pragma unroll
                for (int i = 1; i < NS; i++) m = fmaxf(m, s[i]);
                float e[NS], sum = 0.f;
                #pragma unroll
                for (int i = 0; i < NS; i++) { e[i] = __expf(s[i] - m); sum += e[i]; }
                float inv = __fdividef(1.f, sum);
                #pragma unroll
                for (int i = 0; i < NS; i++) wsm[lane][i] = e[i] * inv;
            }
        }

        // ---- loader warps: deposit t+1, issue LDG t+2 ----
        if (warp >= 10) {
            if (pfrow >= 0) {
                if (pfrow < 10) *(float4*)&pbufA[par ^ 1][pfrow][lq]      = pvA;
                else            *(float4*)&pbufC[par ^ 1][pfrow - 10][lq] = pvA;
            }
            if (pfH) *(float4*)&hbuf[par ^ 1][lbl][lq] = pvH;
            pfrow = -1; pfH = false;
            const int tload = t + 2;
            if (tload < S) {
                if (lrow < 10) {
                    int jbl = lrow / NS, ji = lrow % NS, j = tload - NS + ji;
                    if (j >= 0) {
                        pvA = __ldcs((const float4*)&g_A[((size_t)(b0 + jbl) * S + j) * D + col0 + lq]);
                        pfrow = lrow;
                    }
                } else {
                    pvA = __ldcs((const float4*)&g_C[((size_t)(b0 + lrow - 10) * S + tload) * D + col0 + lq]);
                    pfrow = lrow;
                }
                if (lidx < 32) {
                    pvH = *(const float4*)&Hm[((size_t)(b0 + lbl) * S + tload) * D + col0 + lq];
                    pfH = true;
                }
            }
        }
        __syncthreads();

        // ---- htilde (own cols) ----
        if (tid < BPC * COLS) {
            const int bl = tid >> 6, dd = tid & 63;
            float hh = 0.f;
            #pragma unroll
            for (int i = 0; i < NS; i++) {
                int j = t - NS + i;
                if (j >= 0) hh += wsm[bl][i] * thist[j % NS][bl][dd];
            }
            float hv = hbuf[par][bl][dd] + fmaxf(hh, 0.f);
            thist[t % NS][bl][dd] = hv;
            hdup[bl][dd] = make_float2(hv, hv);
            __stcs(&out[((size_t)(b0 + bl) * S + t) * D + col0 + dd], hv);
        }
        __syncthreads();

        if (t < S - 1) {
            // ---- P3: partial g over k-half, 2 cols x 2 batches ----
            uint64_t acc0 = 0ull, acc1 = 0ull;
            #pragma unroll
            for (int kk = 0; kk < 32; kk++) {
                const int k = khalf * 32 + kk;
                acc0 = fma2(*(uint64_t*)&hdup[0][k], w3p[kk], acc0);
                acc1 = fma2(*(uint64_t*)&hdup[1][k], w3p[kk], acc1);
            }
            stasync_b64_pre(grd0, grm[par], acc0);
            stasync_b64_pre(grd1, grm[par], acc1);

            // ---- P1-pre for t+1 (i<4 warps) ----
            if (warp < 10 && p1i != NS - 1) {
                float2 c2 = *(float2*)&pbufC[par ^ 1][p1bl][d0];
                float x0 = c2.x, x1 = c2.y;
                const int j = (t + 1) - NS + p1i;
                if (j >= 0) {
                    float2 a2 = *(float2*)&pbufA[par ^ 1][warp][d0];
                    float2 g2 = *(float2*)&ghist[j % NS][p1bl][d0];
                    x0 += a2.x + g2.x;
                    x1 += a2.y + g2.y;
                }
                float val = ftanh(x0) * vsm[d0] + ftanh(x1) * vsm[d0 + 1];
                #pragma unroll
                for (int o = 16; o > 0; o >>= 1)
                    val += __shfl_down_sync(0xffffffffu, val, o);
                if (lane == 0) {
                    #pragma unroll
                    for (int r = 0; r < RANKS; r++)
                        stasync_b32(spush[par ^ 1], ms_base + 8 * ((t + 1) & 3), r,
                                    __float_as_uint(val));
                }
            }
        }
    }

    // Terminal cluster sync: no CTA exits while peers' remote stores could
    // still target its SMEM / mbarriers.
    cluster_sync();
}

// ============================================================
// Launch
// ============================================================
extern "C" void kernel_launch(void* const* d_in, const int* in_sizes, int n_in,
                              void* d_out, int out_size)
{
    (void)in_sizes; (void)n_in; (void)out_size;
    const float* H  = (const float*)d_in[0];
    const float* v  = (const float*)d_in[1];
    const float* W1 = (const float*)d_in[2];
    const float* W2 = (const float*)d_in[3];
    const float* W3 = (const float*)d_in[4];
    float* out = (float*)d_out;

    precompute_kernel<<<dim3((B * S) / PM, 8), 256>>>(H, W1, W2);
    recurrent_kernel<<<NCLUSTERS * RANKS, RTHREADS>>>(H, v, W3, out);
}